// round 5
// baseline (speedup 1.0000x reference)
#include <cuda_runtime.h>
#include <math.h>
#include <stdint.h>

#define NN   2048
#define KK   16384      // NN * 8
#define TAU  10
#define NB   8

// dense trace vector for layer 0
__device__ __align__(16) float g_x0[KK];
// spike bitmasks: g_bits[0] = layer-0 spikes (input of layer 1),
//                 g_bits[1] = layer-1 spikes (input of layer 2)
__device__ unsigned int g_bits[2][NN / 32];

// ---------------- Threefry-2x32 (JAX-compatible, 20 rounds) ----------------
__host__ __device__ inline uint32_t tf_rotl(uint32_t v, int r) {
    return (v << r) | (v >> (32 - r));
}

__host__ __device__ inline void tf_block(uint32_t k0, uint32_t k1,
                                         uint32_t c0, uint32_t c1,
                                         uint32_t& o0, uint32_t& o1) {
    uint32_t ks2 = k0 ^ k1 ^ 0x1BD11BDAu;
    uint32_t x0 = c0 + k0, x1 = c1 + k1;
#define TF_RND(r) { x0 += x1; x1 = tf_rotl(x1, (r)); x1 ^= x0; }
    TF_RND(13) TF_RND(15) TF_RND(26) TF_RND(6)
    x0 += k1;  x1 += ks2 + 1u;
    TF_RND(17) TF_RND(29) TF_RND(16) TF_RND(24)
    x0 += ks2; x1 += k0 + 2u;
    TF_RND(13) TF_RND(15) TF_RND(26) TF_RND(6)
    x0 += k0;  x1 += k1 + 3u;
    TF_RND(17) TF_RND(29) TF_RND(16) TF_RND(24)
    x0 += k1;  x1 += ks2 + 4u;
    TF_RND(13) TF_RND(15) TF_RND(26) TF_RND(6)
    x0 += ks2; x1 += k0 + 5u;
#undef TF_RND
    o0 = x0; o1 = x1;
}

__device__ inline float tf_uniform(uint32_t k0, uint32_t k1, uint32_t e) {
    uint32_t b1, b2;
    tf_block(k0, k1, 0u, e, b1, b2);
    uint32_t bits = b1 ^ b2;
    return __uint_as_float((bits >> 9) | 0x3f800000u) - 1.0f;
}

// ---------------- Kernel 1: layer-0 input trace (+ zero the bitmasks) -----
__global__ void trace_kernel(const float* __restrict__ inp) {
    __shared__ float filt[TAU * NB];
    int tid = threadIdx.x;
    if (blockIdx.x == 0 && tid < 2 * (NN / 32)) {
        ((unsigned int*)g_bits)[tid] = 0u;
    }
    if (tid < TAU * NB) {
        int t = tid / NB, b = tid % NB;
        const float mupi = 1.5707963267948966f;
        const float pif  = 3.14159265358979f;
        float arg = mupi * log1pf((float)t) - mupi * (float)b;
        arg = fminf(fmaxf(arg, -pif), pif);
        filt[tid] = 0.5f * (1.0f + cosf(arg));
    }
    __syncthreads();
    int i = blockIdx.x * blockDim.x + tid;
    if (i < NN) {
        float acc[NB];
#pragma unroll
        for (int b = 0; b < NB; b++) acc[b] = 0.0f;
#pragma unroll
        for (int t = 0; t < TAU; t++) {
            float v = inp[i * TAU + (TAU - 1 - t)];
#pragma unroll
            for (int b = 0; b < NB; b++) acc[b] += v * filt[t * NB + b];
        }
#pragma unroll
        for (int b = 0; b < NB; b++) g_x0[i * NB + b] = acc[b];
    }
}

// block-wide reduce over 128 threads (4 warps); result valid in thread 0
__device__ inline float block_reduce_128(float acc) {
    __shared__ float warpsum[4];
#pragma unroll
    for (int off = 16; off > 0; off >>= 1)
        acc += __shfl_down_sync(0xffffffffu, acc, off);
    int lane = threadIdx.x & 31, wid = threadIdx.x >> 5;
    if (lane == 0) warpsum[wid] = acc;
    __syncthreads();
    float tot = 0.0f;
    if (threadIdx.x == 0) {
#pragma unroll
        for (int w = 0; w < 4; w++) tot += warpsum[w];
    }
    return tot;
}

// ---------------- Kernel 2: layer 0, dense matvec -------------------------
// 128 threads/block, 1 row/block: 2048 blocks x 4 warps = 16 blocks/SM
// resident -> the whole grid is a single wave (no quantization tail).
__global__ __launch_bounds__(128, 16) void layer0_kernel(
    const float* __restrict__ W, const float* __restrict__ bias,
    float* __restrict__ p_out, float* __restrict__ s_out,
    uint32_t key0, uint32_t key1)
{
    const int row = blockIdx.x;
    const float4* w4 = reinterpret_cast<const float4*>(W + (size_t)row * KK);
    const float4* x4 = reinterpret_cast<const float4*>(g_x0);

    float acc = 0.0f;
#pragma unroll 8
    for (int it = 0; it < 32; it++) {
        int j = it * 128 + threadIdx.x;
        float4 w = __ldcs(&w4[j]);
        float4 xv = x4[j];
        acc += w.x * xv.x + w.y * xv.y + w.z * xv.z + w.w * xv.w;
    }

    float tot = block_reduce_128(acc);
    if (threadIdx.x == 0) {
        float z = tot + bias[row];
        float p = 1.0f / (1.0f + expf(-z));
        float u = tf_uniform(key0, key1, (uint32_t)row);
        float s = (u < p) ? 1.0f : 0.0f;
        p_out[row] = p;
        s_out[row] = s;
        if (s > 0.0f)
            atomicOr(&g_bits[0][row >> 5], 1u << (row & 31));
    }
}

// ---------------- Kernel 3: layers 1/2 — bitmask matvec -------------------
// pot[row] = sum over spiking i of (W[row,i,0] + f1 * W[row,i,1]).
// 128 threads/block, 1 row/block -> single resident wave.
__global__ __launch_bounds__(128, 16) void layer_sparse(
    const float* __restrict__ W, const float* __restrict__ bias,
    int mask_in, int mask_out,
    float* __restrict__ p_out, float* __restrict__ s_out,
    uint32_t key0, uint32_t key1, float f1)
{
    __shared__ unsigned int sm_bits[NN / 32];
    if (threadIdx.x < NN / 32)
        sm_bits[threadIdx.x] = g_bits[mask_in][threadIdx.x];
    __syncthreads();

    const int row = blockIdx.x;
    const float2* __restrict__ w2 =
        reinterpret_cast<const float2*>(W + (size_t)row * KK);

    float acc = 0.0f;
#pragma unroll 8
    for (int it = 0; it < 16; it++) {
        int i = it * 128 + threadIdx.x;           // input index
        float2 v = __ldcs(&w2[(size_t)i * 4]);    // W[row,i,0..1]
        unsigned int bit = (sm_bits[i >> 5] >> (i & 31)) & 1u;
        float m = bit ? 1.0f : 0.0f;
        acc += m * (v.x + f1 * v.y);
    }

    float tot = block_reduce_128(acc);
    if (threadIdx.x == 0) {
        float z = tot + bias[row];
        float p = 1.0f / (1.0f + expf(-z));
        float u = tf_uniform(key0, key1, (uint32_t)row);
        float s = (u < p) ? 1.0f : 0.0f;
        p_out[row] = p;
        s_out[row] = s;
        if (mask_out >= 0 && s > 0.0f)
            atomicOr(&g_bits[mask_out][row >> 5], 1u << (row & 31));
    }
}

extern "C" void kernel_launch(void* const* d_in, const int* in_sizes, int n_in,
                              void* d_out, int out_size) {
    const float* inp  = (const float*)d_in[0];
    const float* ffw0 = (const float*)d_in[1];
    const float* b0   = (const float*)d_in[3];
    const float* ffw1 = (const float*)d_in[4];
    const float* b1   = (const float*)d_in[6];
    const float* ffw2 = (const float*)d_in[7];
    const float* b2   = (const float*)d_in[9];
    float* out = (float*)d_out;

    // root key = (0, 42); partitionable split: key_i = block(root, (0, i))
    uint32_t k0a, k0b, k1a, k1b, k2a, k2b;
    tf_block(0u, 42u, 0u, 0u, k0a, k0b);
    tf_block(0u, 42u, 0u, 1u, k1a, k1b);
    tf_block(0u, 42u, 0u, 2u, k2a, k2b);

    // FF_FILT[0,1]; entries b>=2 are exactly 0 (clip to -pi), b=0 is exactly 1
    const float mupi = 1.5707963267948966f;
    const float pif  = 3.14159265358979f;
    float f1 = 0.5f * (1.0f + cosf(fminf(fmaxf(-mupi, -pif), pif)));  // ~0.5

    // output layout: [p2 | s2 | p0 | p1 | s0 | s1], 6 * 2048 floats
    float* p2 = out;
    float* s2 = out + 2048;
    float* p0 = out + 4096;
    float* p1 = out + 6144;
    float* s0 = out + 8192;
    float* s1 = out + 10240;

    trace_kernel<<<16, 128>>>(inp);
    layer0_kernel<<<NN, 128>>>(ffw0, b0, p0, s0, k0a, k0b);
    layer_sparse<<<NN, 128>>>(ffw1, b1, 0,  1, p1, s1, k1a, k1b, f1);
    layer_sparse<<<NN, 128>>>(ffw2, b2, 1, -1, p2, s2, k2a, k2b, f1);
}

// round 6
// speedup vs baseline: 1.0570x; 1.0570x over previous
#include <cuda_runtime.h>
#include <math.h>
#include <stdint.h>

#define NN   2048
#define KK   16384      // NN * 8
#define TAU  10
#define NB   8

// dense trace vector for layer 0
__device__ __align__(16) float g_x0[KK];
// spike bitmasks: g_bits[0] = layer-0 spikes (input of layer 1),
//                 g_bits[1] = layer-1 spikes (input of layer 2)
__device__ unsigned int g_bits[2][NN / 32];

// ---------------- Threefry-2x32 (JAX-compatible, 20 rounds) ----------------
__host__ __device__ inline uint32_t tf_rotl(uint32_t v, int r) {
    return (v << r) | (v >> (32 - r));
}

__host__ __device__ inline void tf_block(uint32_t k0, uint32_t k1,
                                         uint32_t c0, uint32_t c1,
                                         uint32_t& o0, uint32_t& o1) {
    uint32_t ks2 = k0 ^ k1 ^ 0x1BD11BDAu;
    uint32_t x0 = c0 + k0, x1 = c1 + k1;
#define TF_RND(r) { x0 += x1; x1 = tf_rotl(x1, (r)); x1 ^= x0; }
    TF_RND(13) TF_RND(15) TF_RND(26) TF_RND(6)
    x0 += k1;  x1 += ks2 + 1u;
    TF_RND(17) TF_RND(29) TF_RND(16) TF_RND(24)
    x0 += ks2; x1 += k0 + 2u;
    TF_RND(13) TF_RND(15) TF_RND(26) TF_RND(6)
    x0 += k0;  x1 += k1 + 3u;
    TF_RND(17) TF_RND(29) TF_RND(16) TF_RND(24)
    x0 += k1;  x1 += ks2 + 4u;
    TF_RND(13) TF_RND(15) TF_RND(26) TF_RND(6)
    x0 += ks2; x1 += k0 + 5u;
#undef TF_RND
    o0 = x0; o1 = x1;
}

__device__ inline float tf_uniform(uint32_t k0, uint32_t k1, uint32_t e) {
    uint32_t b1, b2;
    tf_block(k0, k1, 0u, e, b1, b2);
    uint32_t bits = b1 ^ b2;
    return __uint_as_float((bits >> 9) | 0x3f800000u) - 1.0f;
}

// ---------------- Kernel 1: layer-0 input trace (+ zero the bitmasks) -----
__global__ void trace_kernel(const float* __restrict__ inp) {
    __shared__ float filt[TAU * NB];
    int tid = threadIdx.x;
    if (blockIdx.x == 0 && tid < 2 * (NN / 32)) {
        ((unsigned int*)g_bits)[tid] = 0u;
    }
    if (tid < TAU * NB) {
        int t = tid / NB, b = tid % NB;
        const float mupi = 1.5707963267948966f;
        const float pif  = 3.14159265358979f;
        float arg = mupi * log1pf((float)t) - mupi * (float)b;
        arg = fminf(fmaxf(arg, -pif), pif);
        filt[tid] = 0.5f * (1.0f + cosf(arg));
    }
    __syncthreads();
    int i = blockIdx.x * blockDim.x + tid;
    if (i < NN) {
        float acc[NB];
#pragma unroll
        for (int b = 0; b < NB; b++) acc[b] = 0.0f;
#pragma unroll
        for (int t = 0; t < TAU; t++) {
            float v = inp[i * TAU + (TAU - 1 - t)];
#pragma unroll
            for (int b = 0; b < NB; b++) acc[b] += v * filt[t * NB + b];
        }
#pragma unroll
        for (int b = 0; b < NB; b++) g_x0[i * NB + b] = acc[b];
    }
}

// block-wide reduce over 256 threads (8 warps); result valid in thread 0
__device__ inline float block_reduce_256(float acc) {
    __shared__ float warpsum[8];
#pragma unroll
    for (int off = 16; off > 0; off >>= 1)
        acc += __shfl_down_sync(0xffffffffu, acc, off);
    int lane = threadIdx.x & 31, wid = threadIdx.x >> 5;
    if (lane == 0) warpsum[wid] = acc;
    __syncthreads();
    float tot = 0.0f;
    if (threadIdx.x == 0) {
#pragma unroll
        for (int w = 0; w < 8; w++) tot += warpsum[w];
    }
    return tot;
}

// ---------------- Kernel 2: layer 0, dense matvec (round-4 config) --------
__global__ __launch_bounds__(256) void layer0_kernel(
    const float* __restrict__ W, const float* __restrict__ bias,
    float* __restrict__ p_out, float* __restrict__ s_out,
    uint32_t key0, uint32_t key1)
{
    const int row = blockIdx.x;
    const float4* w4 = reinterpret_cast<const float4*>(W + (size_t)row * KK);
    const float4* x4 = reinterpret_cast<const float4*>(g_x0);

    float acc = 0.0f;
#pragma unroll
    for (int it = 0; it < 16; it++) {
        int j = it * 256 + threadIdx.x;
        float4 w = w4[j];
        float4 xv = x4[j];
        acc += w.x * xv.x + w.y * xv.y + w.z * xv.z + w.w * xv.w;
    }

    float tot = block_reduce_256(acc);
    if (threadIdx.x == 0) {
        float z = tot + bias[row];
        float p = 1.0f / (1.0f + expf(-z));
        float u = tf_uniform(key0, key1, (uint32_t)row);
        float s = (u < p) ? 1.0f : 0.0f;
        p_out[row] = p;
        s_out[row] = s;
        if (s > 0.0f)
            atomicOr(&g_bits[0][row >> 5], 1u << (row & 31));
    }
}

// ---------------- Kernel 3: layers 1/2 — dense-stream bitmask matvec ------
// pot[row] = sum over spiking i of (W[row,i,0] + f1 * W[row,i,1]).
// The row is streamed FULLY COALESCED as float4 (like layer0, which runs at
// ~80% of HBM spec, vs 71% for the 32B-strided float2 gather). float4 index
// j covers w[i,0..3] when j is even (i = j/2), w[i,4..7] when odd (those
// multiply exact zeros). Odd lanes are pure streamers (m = 0 at runtime).
__global__ __launch_bounds__(256) void layer_sparse(
    const float* __restrict__ W, const float* __restrict__ bias,
    int mask_in, int mask_out,
    float* __restrict__ p_out, float* __restrict__ s_out,
    uint32_t key0, uint32_t key1, float f1)
{
    __shared__ unsigned int sm_bits[NN / 32];
    if (threadIdx.x < NN / 32)
        sm_bits[threadIdx.x] = g_bits[mask_in][threadIdx.x];
    __syncthreads();

    const int row = blockIdx.x;
    const float4* __restrict__ w4 =
        reinterpret_cast<const float4*>(W + (size_t)row * KK);

    // lane parity is constant across iterations: even lanes do the math,
    // odd lanes keep the access pattern dense (runtime m=0, loads stay live)
    const float lane_m = (threadIdx.x & 1) ? 0.0f : 1.0f;

    float acc = 0.0f;
#pragma unroll
    for (int it = 0; it < 16; it++) {
        int j = it * 256 + threadIdx.x;           // float4 index in the row
        float4 w = __ldcs(&w4[j]);
        int i = j >> 1;                           // input index
        unsigned int bit = (sm_bits[i >> 5] >> (i & 31)) & 1u;
        float m = lane_m * (bit ? 1.0f : 0.0f);
        acc += m * (w.x + f1 * w.y);
    }

    float tot = block_reduce_256(acc);
    if (threadIdx.x == 0) {
        float z = tot + bias[row];
        float p = 1.0f / (1.0f + expf(-z));
        float u = tf_uniform(key0, key1, (uint32_t)row);
        float s = (u < p) ? 1.0f : 0.0f;
        p_out[row] = p;
        s_out[row] = s;
        if (mask_out >= 0 && s > 0.0f)
            atomicOr(&g_bits[mask_out][row >> 5], 1u << (row & 31));
    }
}

extern "C" void kernel_launch(void* const* d_in, const int* in_sizes, int n_in,
                              void* d_out, int out_size) {
    const float* inp  = (const float*)d_in[0];
    const float* ffw0 = (const float*)d_in[1];
    const float* b0   = (const float*)d_in[3];
    const float* ffw1 = (const float*)d_in[4];
    const float* b1   = (const float*)d_in[6];
    const float* ffw2 = (const float*)d_in[7];
    const float* b2   = (const float*)d_in[9];
    float* out = (float*)d_out;

    // root key = (0, 42); partitionable split: key_i = block(root, (0, i))
    uint32_t k0a, k0b, k1a, k1b, k2a, k2b;
    tf_block(0u, 42u, 0u, 0u, k0a, k0b);
    tf_block(0u, 42u, 0u, 1u, k1a, k1b);
    tf_block(0u, 42u, 0u, 2u, k2a, k2b);

    // FF_FILT[0,1]; entries b>=2 are exactly 0 (clip to -pi), b=0 is exactly 1
    const float mupi = 1.5707963267948966f;
    const float pif  = 3.14159265358979f;
    float f1 = 0.5f * (1.0f + cosf(fminf(fmaxf(-mupi, -pif), pif)));  // ~0.5

    // output layout: [p2 | s2 | p0 | p1 | s0 | s1], 6 * 2048 floats
    float* p2 = out;
    float* s2 = out + 2048;
    float* p0 = out + 4096;
    float* p1 = out + 6144;
    float* s0 = out + 8192;
    float* s1 = out + 10240;

    trace_kernel<<<16, 128>>>(inp);
    layer0_kernel<<<NN, 256>>>(ffw0, b0, p0, s0, k0a, k0b);
    layer_sparse<<<NN, 256>>>(ffw1, b1, 0,  1, p1, s1, k1a, k1b, f1);
    layer_sparse<<<NN, 256>>>(ffw2, b2, 1, -1, p2, s2, k2a, k2b, f1);
}

// round 7
// speedup vs baseline: 1.0798x; 1.0216x over previous
#include <cuda_runtime.h>
#include <math.h>
#include <stdint.h>

#define NN   2048
#define KK   16384      // NN * 8
#define TAU  10
#define NB   8

// dense trace vector for layer 0
__device__ __align__(16) float g_x0[KK];
// spike bitmasks: g_bits[0] = layer-0 spikes (input of layer 1),
//                 g_bits[1] = layer-1 spikes (input of layer 2)
__device__ unsigned int g_bits[2][NN / 32];

// ---------------- Threefry-2x32 (JAX-compatible, 20 rounds) ----------------
__host__ __device__ inline uint32_t tf_rotl(uint32_t v, int r) {
    return (v << r) | (v >> (32 - r));
}

__host__ __device__ inline void tf_block(uint32_t k0, uint32_t k1,
                                         uint32_t c0, uint32_t c1,
                                         uint32_t& o0, uint32_t& o1) {
    uint32_t ks2 = k0 ^ k1 ^ 0x1BD11BDAu;
    uint32_t x0 = c0 + k0, x1 = c1 + k1;
#define TF_RND(r) { x0 += x1; x1 = tf_rotl(x1, (r)); x1 ^= x0; }
    TF_RND(13) TF_RND(15) TF_RND(26) TF_RND(6)
    x0 += k1;  x1 += ks2 + 1u;
    TF_RND(17) TF_RND(29) TF_RND(16) TF_RND(24)
    x0 += ks2; x1 += k0 + 2u;
    TF_RND(13) TF_RND(15) TF_RND(26) TF_RND(6)
    x0 += k0;  x1 += k1 + 3u;
    TF_RND(17) TF_RND(29) TF_RND(16) TF_RND(24)
    x0 += k1;  x1 += ks2 + 4u;
    TF_RND(13) TF_RND(15) TF_RND(26) TF_RND(6)
    x0 += ks2; x1 += k0 + 5u;
#undef TF_RND
    o0 = x0; o1 = x1;
}

__device__ inline float tf_uniform(uint32_t k0, uint32_t k1, uint32_t e) {
    uint32_t b1, b2;
    tf_block(k0, k1, 0u, e, b1, b2);
    uint32_t bits = b1 ^ b2;
    return __uint_as_float((bits >> 9) | 0x3f800000u) - 1.0f;
}

// ---------------- Kernel 1: layer-0 input trace (+ zero the bitmasks) -----
__global__ void trace_kernel(const float* __restrict__ inp) {
    __shared__ float filt[TAU * NB];
    int tid = threadIdx.x;
    if (blockIdx.x == 0 && tid < 2 * (NN / 32)) {
        ((unsigned int*)g_bits)[tid] = 0u;
    }
    if (tid < TAU * NB) {
        int t = tid / NB, b = tid % NB;
        const float mupi = 1.5707963267948966f;
        const float pif  = 3.14159265358979f;
        float arg = mupi * log1pf((float)t) - mupi * (float)b;
        arg = fminf(fmaxf(arg, -pif), pif);
        filt[tid] = 0.5f * (1.0f + cosf(arg));
    }
    __syncthreads();
    int i = blockIdx.x * blockDim.x + tid;
    if (i < NN) {
        float acc[NB];
#pragma unroll
        for (int b = 0; b < NB; b++) acc[b] = 0.0f;
#pragma unroll
        for (int t = 0; t < TAU; t++) {
            float v = inp[i * TAU + (TAU - 1 - t)];
#pragma unroll
            for (int b = 0; b < NB; b++) acc[b] += v * filt[t * NB + b];
        }
#pragma unroll
        for (int b = 0; b < NB; b++) g_x0[i * NB + b] = acc[b];
    }
}

// block-wide reduce over 256 threads (8 warps); result valid in thread 0
__device__ inline float block_reduce_256(float acc) {
    __shared__ float warpsum[8];
#pragma unroll
    for (int off = 16; off > 0; off >>= 1)
        acc += __shfl_down_sync(0xffffffffu, acc, off);
    int lane = threadIdx.x & 31, wid = threadIdx.x >> 5;
    if (lane == 0) warpsum[wid] = acc;
    __syncthreads();
    float tot = 0.0f;
    if (threadIdx.x == 0) {
#pragma unroll
        for (int w = 0; w < 8; w++) tot += warpsum[w];
    }
    return tot;
}

// ---------------- Kernel 2: layer 0, dense matvec (plain loads) -----------
__global__ __launch_bounds__(256) void layer0_kernel(
    const float* __restrict__ W, const float* __restrict__ bias,
    float* __restrict__ p_out, float* __restrict__ s_out,
    uint32_t key0, uint32_t key1)
{
    const int row = blockIdx.x;
    const float4* w4 = reinterpret_cast<const float4*>(W + (size_t)row * KK);
    const float4* x4 = reinterpret_cast<const float4*>(g_x0);

    float acc = 0.0f;
#pragma unroll
    for (int it = 0; it < 16; it++) {
        int j = it * 256 + threadIdx.x;
        float4 w = w4[j];
        float4 xv = x4[j];
        acc += w.x * xv.x + w.y * xv.y + w.z * xv.z + w.w * xv.w;
    }

    float tot = block_reduce_256(acc);
    if (threadIdx.x == 0) {
        float z = tot + bias[row];
        float p = 1.0f / (1.0f + expf(-z));
        float u = tf_uniform(key0, key1, (uint32_t)row);
        float s = (u < p) ? 1.0f : 0.0f;
        p_out[row] = p;
        s_out[row] = s;
        if (s > 0.0f)
            atomicOr(&g_bits[0][row >> 5], 1u << (row & 31));
    }
}

// ---------------- Kernel 3: layers 1/2 — dense-stream bitmask matvec ------
// pot[row] = sum over spiking i of (W[row,i,0] + f1 * W[row,i,1]).
// Identical to round 6 EXCEPT: plain LDG instead of __ldcs. Evidence across
// rounds shows .CS (evict-first) loads cap DRAM at ~72% while plain loads on
// the identical streaming pattern reach ~83% (layer0).
__global__ __launch_bounds__(256) void layer_sparse(
    const float* __restrict__ W, const float* __restrict__ bias,
    int mask_in, int mask_out,
    float* __restrict__ p_out, float* __restrict__ s_out,
    uint32_t key0, uint32_t key1, float f1)
{
    __shared__ unsigned int sm_bits[NN / 32];
    if (threadIdx.x < NN / 32)
        sm_bits[threadIdx.x] = g_bits[mask_in][threadIdx.x];
    __syncthreads();

    const int row = blockIdx.x;
    const float4* __restrict__ w4 =
        reinterpret_cast<const float4*>(W + (size_t)row * KK);

    // even float4s hold w[i,0..3] (i = j/2); odd float4s hold w[i,4..7]
    // which multiply exact zeros. Odd lanes stream with runtime m = 0.
    const float lane_m = (threadIdx.x & 1) ? 0.0f : 1.0f;

    float acc = 0.0f;
#pragma unroll
    for (int it = 0; it < 16; it++) {
        int j = it * 256 + threadIdx.x;           // float4 index in the row
        float4 w = w4[j];                         // plain LDG (no .cs)
        int i = j >> 1;                           // input index
        unsigned int bit = (sm_bits[i >> 5] >> (i & 31)) & 1u;
        float m = lane_m * (bit ? 1.0f : 0.0f);
        acc += m * (w.x + f1 * w.y);
    }

    float tot = block_reduce_256(acc);
    if (threadIdx.x == 0) {
        float z = tot + bias[row];
        float p = 1.0f / (1.0f + expf(-z));
        float u = tf_uniform(key0, key1, (uint32_t)row);
        float s = (u < p) ? 1.0f : 0.0f;
        p_out[row] = p;
        s_out[row] = s;
        if (mask_out >= 0 && s > 0.0f)
            atomicOr(&g_bits[mask_out][row >> 5], 1u << (row & 31));
    }
}

extern "C" void kernel_launch(void* const* d_in, const int* in_sizes, int n_in,
                              void* d_out, int out_size) {
    const float* inp  = (const float*)d_in[0];
    const float* ffw0 = (const float*)d_in[1];
    const float* b0   = (const float*)d_in[3];
    const float* ffw1 = (const float*)d_in[4];
    const float* b1   = (const float*)d_in[6];
    const float* ffw2 = (const float*)d_in[7];
    const float* b2   = (const float*)d_in[9];
    float* out = (float*)d_out;

    // root key = (0, 42); partitionable split: key_i = block(root, (0, i))
    uint32_t k0a, k0b, k1a, k1b, k2a, k2b;
    tf_block(0u, 42u, 0u, 0u, k0a, k0b);
    tf_block(0u, 42u, 0u, 1u, k1a, k1b);
    tf_block(0u, 42u, 0u, 2u, k2a, k2b);

    // FF_FILT[0,1]; entries b>=2 are exactly 0 (clip to -pi), b=0 is exactly 1
    const float mupi = 1.5707963267948966f;
    const float pif  = 3.14159265358979f;
    float f1 = 0.5f * (1.0f + cosf(fminf(fmaxf(-mupi, -pif), pif)));  // ~0.5

    // output layout: [p2 | s2 | p0 | p1 | s0 | s1], 6 * 2048 floats
    float* p2 = out;
    float* s2 = out + 2048;
    float* p0 = out + 4096;
    float* p1 = out + 6144;
    float* s0 = out + 8192;
    float* s1 = out + 10240;

    trace_kernel<<<16, 128>>>(inp);
    layer0_kernel<<<NN, 256>>>(ffw0, b0, p0, s0, k0a, k0b);
    layer_sparse<<<NN, 256>>>(ffw1, b1, 0,  1, p1, s1, k1a, k1b, f1);
    layer_sparse<<<NN, 256>>>(ffw2, b2, 1, -1, p2, s2, k2a, k2b, f1);
}

// round 8
// speedup vs baseline: 1.0808x; 1.0009x over previous
#include <cuda_runtime.h>
#include <math.h>
#include <stdint.h>

#define NN   2048
#define KK   16384      // NN * 8
#define TAU  10
#define NB   8

// dense trace vector for layer 0
__device__ __align__(16) float g_x0[KK];
// spike bitmasks: g_bits[0] = layer-0 spikes, g_bits[1] = layer-1 spikes
__device__ unsigned int g_bits[2][NN / 32];

// ---------------- Threefry-2x32 (JAX-compatible, 20 rounds) ----------------
__host__ __device__ inline uint32_t tf_rotl(uint32_t v, int r) {
    return (v << r) | (v >> (32 - r));
}

__host__ __device__ inline void tf_block(uint32_t k0, uint32_t k1,
                                         uint32_t c0, uint32_t c1,
                                         uint32_t& o0, uint32_t& o1) {
    uint32_t ks2 = k0 ^ k1 ^ 0x1BD11BDAu;
    uint32_t x0 = c0 + k0, x1 = c1 + k1;
#define TF_RND(r) { x0 += x1; x1 = tf_rotl(x1, (r)); x1 ^= x0; }
    TF_RND(13) TF_RND(15) TF_RND(26) TF_RND(6)
    x0 += k1;  x1 += ks2 + 1u;
    TF_RND(17) TF_RND(29) TF_RND(16) TF_RND(24)
    x0 += ks2; x1 += k0 + 2u;
    TF_RND(13) TF_RND(15) TF_RND(26) TF_RND(6)
    x0 += k0;  x1 += k1 + 3u;
    TF_RND(17) TF_RND(29) TF_RND(16) TF_RND(24)
    x0 += k1;  x1 += ks2 + 4u;
    TF_RND(13) TF_RND(15) TF_RND(26) TF_RND(6)
    x0 += ks2; x1 += k0 + 5u;
#undef TF_RND
    o0 = x0; o1 = x1;
}

__device__ inline float tf_uniform(uint32_t k0, uint32_t k1, uint32_t e) {
    uint32_t b1, b2;
    tf_block(k0, k1, 0u, e, b1, b2);
    uint32_t bits = b1 ^ b2;
    return __uint_as_float((bits >> 9) | 0x3f800000u) - 1.0f;
}

// ---------------- Kernel 1: layer-0 input trace (+ zero the bitmasks) -----
__global__ void trace_kernel(const float* __restrict__ inp) {
    __shared__ float filt[TAU * NB];
    int tid = threadIdx.x;
    if (blockIdx.x == 0 && tid < 2 * (NN / 32)) {
        ((unsigned int*)g_bits)[tid] = 0u;
    }
    if (tid < TAU * NB) {
        int t = tid / NB, b = tid % NB;
        const float mupi = 1.5707963267948966f;
        const float pif  = 3.14159265358979f;
        float arg = mupi * log1pf((float)t) - mupi * (float)b;
        arg = fminf(fmaxf(arg, -pif), pif);
        filt[tid] = 0.5f * (1.0f + cosf(arg));
    }
    __syncthreads();
    int i = blockIdx.x * blockDim.x + tid;
    if (i < NN) {
        float acc[NB];
#pragma unroll
        for (int b = 0; b < NB; b++) acc[b] = 0.0f;
#pragma unroll
        for (int t = 0; t < TAU; t++) {
            float v = inp[i * TAU + (TAU - 1 - t)];
#pragma unroll
            for (int b = 0; b < NB; b++) acc[b] += v * filt[t * NB + b];
        }
#pragma unroll
        for (int b = 0; b < NB; b++) g_x0[i * NB + b] = acc[b];
    }
}

// block-wide reduce over 256 threads (8 warps); result valid in thread 0
__device__ inline float block_reduce_256(float acc, float* warpsum) {
#pragma unroll
    for (int off = 16; off > 0; off >>= 1)
        acc += __shfl_down_sync(0xffffffffu, acc, off);
    int lane = threadIdx.x & 31, wid = threadIdx.x >> 5;
    if (lane == 0) warpsum[wid] = acc;
    __syncthreads();
    float tot = 0.0f;
    if (threadIdx.x == 0) {
#pragma unroll
        for (int w = 0; w < 8; w++) tot += warpsum[w];
    }
    return tot;
}

// ---------------- Kernel 2: layer 0, dense matvec (unchanged, best) -------
__global__ __launch_bounds__(256) void layer0_kernel(
    const float* __restrict__ W, const float* __restrict__ bias,
    float* __restrict__ p_out, float* __restrict__ s_out,
    uint32_t key0, uint32_t key1)
{
    __shared__ float warpsum[8];
    const int row = blockIdx.x;
    const float4* w4 = reinterpret_cast<const float4*>(W + (size_t)row * KK);
    const float4* x4 = reinterpret_cast<const float4*>(g_x0);

    float acc = 0.0f;
#pragma unroll
    for (int it = 0; it < 16; it++) {
        int j = it * 256 + threadIdx.x;
        float4 w = w4[j];
        float4 xv = x4[j];
        acc += w.x * xv.x + w.y * xv.y + w.z * xv.z + w.w * xv.w;
    }

    float tot = block_reduce_256(acc, warpsum);
    if (threadIdx.x == 0) {
        float z = tot + bias[row];
        float p = 1.0f / (1.0f + expf(-z));
        float u = tf_uniform(key0, key1, (uint32_t)row);
        float s = (u < p) ? 1.0f : 0.0f;
        p_out[row] = p;
        s_out[row] = s;
        if (s > 0.0f)
            atomicOr(&g_bits[0][row >> 5], 1u << (row & 31));
    }
}

// ---------------- Kernel 3: layers 1/2 — pair-granular sparse gather ------
// A "pair" p = inputs (2p, 2p+1) spans one 64B DRAM fill block
// (bytes [64p, 64p+64) of the row). Only pairs with >=1 spiking member are
// touched: DRAM traffic ~ (1-(1-d)^2) * 128MB ≈ 100MB at d=0.5 (or 64MB if
// fills turn out to be 32B-granular, since member loads are predicated).
__global__ __launch_bounds__(256) void layer_pair(
    const float* __restrict__ W, const float* __restrict__ bias,
    int mask_in, int mask_out,
    float* __restrict__ p_out, float* __restrict__ s_out,
    uint32_t key0, uint32_t key1, float f1)
{
    __shared__ unsigned int sm_bits[NN / 32];          // 64 words
    __shared__ unsigned short sm_pairs[NN / 2];        // ascending active pairs
    __shared__ int sm_warp[8];
    __shared__ int sm_cnt;
    __shared__ float warpsum[8];

    const int t = threadIdx.x;
    if (t < NN / 32) sm_bits[t] = g_bits[mask_in][t];
    __syncthreads();

    // ---- build active-pair list (deterministic, ascending) ----
    // thread t owns pairs 4t..4t+3; all 8 of their spike bits live in
    // sm_bits[t>>2], byte (t&3).
    const unsigned int word = sm_bits[t >> 2];
    unsigned int f[4];
    int c = 0;
#pragma unroll
    for (int q = 0; q < 4; q++) {
        f[q] = (word >> ((t & 3) * 8 + 2 * q)) & 3u;   // bits of (2p, 2p+1)
        c += (f[q] != 0u);
    }
    // warp-inclusive scan of c
    int lane = t & 31, wid = t >> 5;
    int incl = c;
#pragma unroll
    for (int off = 1; off < 32; off <<= 1) {
        int v = __shfl_up_sync(0xffffffffu, incl, off);
        if (lane >= off) incl += v;
    }
    if (lane == 31) sm_warp[wid] = incl;
    __syncthreads();
    if (t == 0) {
        int run = 0;
#pragma unroll
        for (int w = 0; w < 8; w++) { int v = sm_warp[w]; sm_warp[w] = run; run += v; }
        sm_cnt = run;
    }
    __syncthreads();
    int o = sm_warp[wid] + (incl - c);
#pragma unroll
    for (int q = 0; q < 4; q++) {
        if (f[q] != 0u) sm_pairs[o++] = (unsigned short)(4 * t + q);
    }
    __syncthreads();

    const int cnt = sm_cnt;
    const int row = blockIdx.x;
    const float2* __restrict__ w2 =
        reinterpret_cast<const float2*>(W + (size_t)row * KK);

    // ---- gather: up to 4 pairs/thread, 8 predicated loads in flight ----
    int   pk[4];
    float2 A[4], B[4];
#pragma unroll
    for (int q = 0; q < 4; q++) {
        int k = t + q * 256;
        bool v = (k < cnt);
        int p = v ? (int)sm_pairs[k] : 0;
        pk[q] = p;
        unsigned int bb = v ? ((sm_bits[p >> 4] >> ((p & 15) * 2)) & 3u) : 0u;
        A[q] = (bb & 1u) ? w2[(size_t)p * 8]     : make_float2(0.0f, 0.0f);
        B[q] = (bb & 2u) ? w2[(size_t)p * 8 + 4] : make_float2(0.0f, 0.0f);
    }
    float acc = 0.0f;
#pragma unroll
    for (int q = 0; q < 4; q++) {
        acc += (A[q].x + f1 * A[q].y) + (B[q].x + f1 * B[q].y);
    }

    float tot = block_reduce_256(acc, warpsum);
    if (threadIdx.x == 0) {
        float z = tot + bias[row];
        float p = 1.0f / (1.0f + expf(-z));
        float u = tf_uniform(key0, key1, (uint32_t)row);
        float s = (u < p) ? 1.0f : 0.0f;
        p_out[row] = p;
        s_out[row] = s;
        if (mask_out >= 0 && s > 0.0f)
            atomicOr(&g_bits[mask_out][row >> 5], 1u << (row & 31));
    }
}

extern "C" void kernel_launch(void* const* d_in, const int* in_sizes, int n_in,
                              void* d_out, int out_size) {
    const float* inp  = (const float*)d_in[0];
    const float* ffw0 = (const float*)d_in[1];
    const float* b0   = (const float*)d_in[3];
    const float* ffw1 = (const float*)d_in[4];
    const float* b1   = (const float*)d_in[6];
    const float* ffw2 = (const float*)d_in[7];
    const float* b2   = (const float*)d_in[9];
    float* out = (float*)d_out;

    // root key = (0, 42); partitionable split: key_i = block(root, (0, i))
    uint32_t k0a, k0b, k1a, k1b, k2a, k2b;
    tf_block(0u, 42u, 0u, 0u, k0a, k0b);
    tf_block(0u, 42u, 0u, 1u, k1a, k1b);
    tf_block(0u, 42u, 0u, 2u, k2a, k2b);

    // FF_FILT[0,1]; entries b>=2 are exactly 0 (clip to -pi), b=0 is exactly 1
    const float mupi = 1.5707963267948966f;
    const float pif  = 3.14159265358979f;
    float f1 = 0.5f * (1.0f + cosf(fminf(fmaxf(-mupi, -pif), pif)));  // ~0.5

    // output layout: [p2 | s2 | p0 | p1 | s0 | s1], 6 * 2048 floats
    float* p2 = out;
    float* s2 = out + 2048;
    float* p0 = out + 4096;
    float* p1 = out + 6144;
    float* s0 = out + 8192;
    float* s1 = out + 10240;

    trace_kernel<<<16, 128>>>(inp);
    layer0_kernel<<<NN, 256>>>(ffw0, b0, p0, s0, k0a, k0b);
    layer_pair<<<NN, 256>>>(ffw1, b1, 0,  1, p1, s1, k1a, k1b, f1);
    layer_pair<<<NN, 256>>>(ffw2, b2, 1, -1, p2, s2, k2a, k2b, f1);
}